// round 13
// baseline (speedup 1.0000x reference)
#include <cuda_runtime.h>

#define NNODES 100000
#define NEDGES 1600000
typedef unsigned long long ull;

// ---------------- scratch (device globals; no allocation) ----------------
__device__ float d_xw[NNODES*32];    // xws = (X@W)*dinv of current GCN layer
__device__ float d_agg[NNODES*32];   // edge aggregation accumulator (reused)
__device__ float d_r1[NNODES*32];    // relu(gcn1) pre-BN
__device__ float d_r2[NNODES*32];    // relu(gcn2) pre-BN
__device__ float d_deg[NNODES];
__device__ float d_dinv[NNODES];
// d_small: [0:32) xsum, [32:64) sum1, [64:96) sq1, [96:128) sum2, [128:160) sq2
__device__ float d_small[160];
// d_prep: [0:32) s1, [32:64) t1, [64:1088) w2p (=diag(s1)@w2), [1088:1120) c2 (=t1@w2)
__device__ float d_prep[1120];
// d_prep2: A1c[3072], A2c[3072], W2c[3072], gb1c[96], gb2c[96], fb1p[32]
__device__ float d_prep2[9440];

// ---------------- helpers ----------------
__device__ __forceinline__ void red_add_v4(float* addr, float a, float b, float c, float d) {
    asm volatile("red.global.add.v4.f32 [%0], {%1,%2,%3,%4};"
                 :: "l"(addr), "f"(a), "f"(b), "f"(c), "f"(d) : "memory");
}
__device__ __forceinline__ float fsig(float x) {
    return __fdividef(1.f, 1.f + __expf(-x));
}
__device__ __forceinline__ float ftanh_(float x) {
    x = fminf(fmaxf(x, -15.f), 15.f);
    float e = __expf(2.f * x);
    return __fdividef(e - 1.f, e + 1.f);
}
#define FMA2(d, a, b, c) asm("fma.rn.f32x2 %0, %1, %2, %3;" : "=l"(d) : "l"(a), "l"(b), "l"(c))
#define MUL2(d, a, b)    asm("mul.rn.f32x2 %0, %1, %2;" : "=l"(d) : "l"(a), "l"(b))
__device__ __forceinline__ ull pack2(float lo, float hi) {
    ull r; asm("mov.b64 %0, {%1, %2};" : "=l"(r) : "f"(lo), "f"(hi)); return r;
}
__device__ __forceinline__ void unpack2(ull v, float& lo, float& hi) {
    asm("mov.b64 {%0, %1}, %2;" : "=f"(lo), "=f"(hi) : "l"(v));
}

// ---------------- kernels ----------------
__global__ void k_zero_all() {
    int i = blockIdx.x * blockDim.x + threadIdx.x;
    int stride = gridDim.x * blockDim.x;
    float4 z = make_float4(0.f, 0.f, 0.f, 0.f);
    for (int j = i; j < NNODES * 8; j += stride)
        reinterpret_cast<float4*>(d_agg)[j] = z;
    if (i < NNODES) d_deg[i] = 0.f;
    if (i < 160) d_small[i] = 0.f;
}

// weighted in-degree: 4 edges per thread, vectorized index loads
__global__ void k_deg(const int* __restrict__ dst, const float* __restrict__ ea) {
    int q = blockIdx.x * blockDim.x + threadIdx.x;
    if (q >= NEDGES / 4) return;
    int4 d4 = __ldg(reinterpret_cast<const int4*>(dst) + q);
    float4 a4 = __ldg(reinterpret_cast<const float4*>(ea) + q);
    atomicAdd(&d_deg[d4.x], a4.x);
    atomicAdd(&d_deg[d4.y], a4.y);
    atomicAdd(&d_deg[d4.z], a4.z);
    atomicAdd(&d_deg[d4.w], a4.w);
}

// column sums of x + fused nodeprep (dinv); runs after k_deg.
__global__ void k_colsum(const float* __restrict__ x) {
    int t = blockIdx.x * blockDim.x + threadIdx.x;
    int stride = gridDim.x * blockDim.x;
    float4 acc = make_float4(0.f, 0.f, 0.f, 0.f);
    const float4* x4 = reinterpret_cast<const float4*>(x);
    for (int i = t; i < NNODES * 8; i += stride) {
        float4 v = __ldg(x4 + i);
        acc.x += v.x; acc.y += v.y; acc.z += v.z; acc.w += v.w;
    }
#pragma unroll
    for (int o = 8; o < 32; o <<= 1) {
        acc.x += __shfl_xor_sync(0xffffffffu, acc.x, o);
        acc.y += __shfl_xor_sync(0xffffffffu, acc.y, o);
        acc.z += __shfl_xor_sync(0xffffffffu, acc.z, o);
        acc.w += __shfl_xor_sync(0xffffffffu, acc.w, o);
    }
    int lane = threadIdx.x & 31;
    if (lane < 8) {
        int g = (t & 7) * 4;
        atomicAdd(&d_small[g + 0], acc.x);
        atomicAdd(&d_small[g + 1], acc.y);
        atomicAdd(&d_small[g + 2], acc.z);
        atomicAdd(&d_small[g + 3], acc.w);
    }
    // fused nodeprep: dinv = rsqrt(deg + 1)
    for (int i = t; i < NNODES; i += stride)
        d_dinv[i] = rsqrtf(d_deg[i] + 1.f);
}

// xws = (X @ W (+rowbias)) * dinv[node], f32x2 packed; 128-thread blocks for occupancy.
template<int L>
__global__ __launch_bounds__(128) void k_gemm(const float* __restrict__ Xin,
                                              const float* __restrict__ Win) {
    __shared__ float xs[128 * 33];
    __shared__ float ws[1024];
    __shared__ float bs[32];
    int t = threadIdx.x;
    int base = blockIdx.x * 128;
    const float* X = (L == 1) ? Xin : d_r1;
    const float* W = (L == 1) ? Win : (d_prep + 64);
    for (int i = t; i < 1024; i += 128) ws[i] = W[i];
    if (t < 32) bs[t] = (L == 1) ? 0.f : d_prep[1088 + t];
    for (int i = t; i < 4096; i += 128) {
        int g = base * 32 + i;
        xs[(i >> 5) * 33 + (i & 31)] = (g < NNODES * 32) ? X[g] : 0.f;
    }
    __syncthreads();
    int node = base + t;
    if (node >= NNODES) return;
    ull out2[16];
    const ull* bs2 = reinterpret_cast<const ull*>(bs);
#pragma unroll
    for (int h2 = 0; h2 < 16; h2++) out2[h2] = bs2[h2];
#pragma unroll
    for (int k = 0; k < 32; k++) {
        float xv = xs[t * 33 + k];
        ull xv2 = pack2(xv, xv);
        const ull* wrow = reinterpret_cast<const ull*>(ws + k * 32);
#pragma unroll
        for (int h2 = 0; h2 < 16; h2++)
            FMA2(out2[h2], xv2, wrow[h2], out2[h2]);
    }
    float dv = __ldg(&d_dinv[node]);
    ull dv2 = pack2(dv, dv);
#pragma unroll
    for (int h2 = 0; h2 < 16; h2++) MUL2(out2[h2], out2[h2], dv2);
    ulonglong2* o2 = reinterpret_cast<ulonglong2*>(d_xw + node * 32);
#pragma unroll
    for (int c = 0; c < 8; c++)
        o2[c] = make_ulonglong2(out2[2*c], out2[2*c+1]);
}

// scatter: group of 8 lanes handles 4 edges; lane's chunk c = t&7.
// 4 independent gathers front-loaded for MLP, then 4 reds. Weight = raw ea.
__global__ void k_edge(const int* __restrict__ src, const int* __restrict__ dst,
                       const float* __restrict__ ea) {
    int t = blockIdx.x * blockDim.x + threadIdx.x;
    int g = t >> 3;                 // edge-quad index
    int c = t & 7;                  // float4 chunk within feature row
    if (g >= NEDGES / 4) return;
    int4 s4 = __ldg(reinterpret_cast<const int4*>(src) + g);
    int4 d4 = __ldg(reinterpret_cast<const int4*>(dst) + g);
    float4 a4 = __ldg(reinterpret_cast<const float4*>(ea) + g);
    const float4* X = reinterpret_cast<const float4*>(d_xw);
    float4 v0 = __ldg(X + s4.x * 8 + c);
    float4 v1 = __ldg(X + s4.y * 8 + c);
    float4 v2 = __ldg(X + s4.z * 8 + c);
    float4 v3 = __ldg(X + s4.w * 8 + c);
    red_add_v4(d_agg + d4.x * 32 + c * 4, v0.x * a4.x, v0.y * a4.x, v0.z * a4.x, v0.w * a4.x);
    red_add_v4(d_agg + d4.y * 32 + c * 4, v1.x * a4.y, v1.y * a4.y, v1.z * a4.y, v1.w * a4.y);
    red_add_v4(d_agg + d4.z * 32 + c * 4, v2.x * a4.z, v2.y * a4.z, v2.z * a4.z, v2.w * a4.z);
    red_add_v4(d_agg + d4.w * 32 + c * 4, v3.x * a4.w, v3.y * a4.w, v3.z * a4.w, v3.w * a4.w);
}

// r = relu((agg + xws)*dinv + b); accumulate BN stats; L==1 also re-zeroes agg.
template<int L>
__global__ void k_post(const float* __restrict__ bias) {
    int t = blockIdx.x * blockDim.x + threadIdx.x;
    int stride = gridDim.x * blockDim.x;
    int g = (t & 7) * 4;
    float4 bf = *reinterpret_cast<const float4*>(bias + g);
    float* R = (L == 1) ? d_r1 : d_r2;
    float4 s = make_float4(0.f, 0.f, 0.f, 0.f);
    float4 q = make_float4(0.f, 0.f, 0.f, 0.f);
    float4* A4 = reinterpret_cast<float4*>(d_agg);
    const float4* X4 = reinterpret_cast<const float4*>(d_xw);
    float4* R4 = reinterpret_cast<float4*>(R);
    float4 z = make_float4(0.f, 0.f, 0.f, 0.f);
    for (int i = t; i < NNODES * 8; i += stride) {
        int node = i >> 3;
        float dv = __ldg(d_dinv + node);
        float4 a = A4[i];
        float4 xw = X4[i];
        float4 v;
        v.x = fmaxf((a.x + xw.x) * dv + bf.x, 0.f);
        v.y = fmaxf((a.y + xw.y) * dv + bf.y, 0.f);
        v.z = fmaxf((a.z + xw.z) * dv + bf.z, 0.f);
        v.w = fmaxf((a.w + xw.w) * dv + bf.w, 0.f);
        R4[i] = v;
        if (L == 1) A4[i] = z;   // re-zero accumulator for layer 2
        s.x += v.x; s.y += v.y; s.z += v.z; s.w += v.w;
        q.x = fmaf(v.x, v.x, q.x); q.y = fmaf(v.y, v.y, q.y);
        q.z = fmaf(v.z, v.z, q.z); q.w = fmaf(v.w, v.w, q.w);
    }
#pragma unroll
    for (int o = 8; o < 32; o <<= 1) {
        s.x += __shfl_xor_sync(0xffffffffu, s.x, o);
        s.y += __shfl_xor_sync(0xffffffffu, s.y, o);
        s.z += __shfl_xor_sync(0xffffffffu, s.z, o);
        s.w += __shfl_xor_sync(0xffffffffu, s.w, o);
        q.x += __shfl_xor_sync(0xffffffffu, q.x, o);
        q.y += __shfl_xor_sync(0xffffffffu, q.y, o);
        q.z += __shfl_xor_sync(0xffffffffu, q.z, o);
        q.w += __shfl_xor_sync(0xffffffffu, q.w, o);
    }
    int lane = threadIdx.x & 31;
    if (lane < 8) {
        int off = (L == 1) ? 32 : 96;
        atomicAdd(&d_small[off + g + 0], s.x);
        atomicAdd(&d_small[off + g + 1], s.y);
        atomicAdd(&d_small[off + g + 2], s.z);
        atomicAdd(&d_small[off + g + 3], s.w);
        atomicAdd(&d_small[off + 32 + g + 0], q.x);
        atomicAdd(&d_small[off + 32 + g + 1], q.y);
        atomicAdd(&d_small[off + 32 + g + 2], q.z);
        atomicAdd(&d_small[off + 32 + g + 3], q.w);
    }
}

// finalize BN1; build w2p = diag(s1)@w2 and c2 = t1@w2  (1 block x 32 threads)
__global__ void k_prep1(const float* __restrict__ g1, const float* __restrict__ be1,
                        const float* __restrict__ w2) {
    __shared__ float t1s[32];
    int f = threadIdx.x;
    float mu = d_small[32 + f] * (1.f / NNODES);
    float var = d_small[64 + f] * (1.f / NNODES) - mu * mu;
    float s = g1[f] * rsqrtf(var + 1e-5f);
    float tt = be1[f] - mu * s;
    t1s[f] = tt;
    d_prep[f] = s; d_prep[32 + f] = tt;
    __syncthreads();
    for (int h = 0; h < 32; h++) d_prep[64 + f * 32 + h] = s * w2[f * 32 + h];
    float c = 0.f;
    for (int k = 0; k < 32; k++) c += t1s[k] * w2[k * 32 + f];
    d_prep[1088 + f] = c;
}

// finalize BN2; fold BN1/BN2 into LSTM1 input matrices; fold skip_avg into fc1 bias.
__global__ void k_prep2(const float* __restrict__ g2, const float* __restrict__ be2,
                        const float* __restrict__ wih1, const float* __restrict__ bih1,
                        const float* __restrict__ bhh1, const float* __restrict__ wih2,
                        const float* __restrict__ bih2, const float* __restrict__ bhh2,
                        const float* __restrict__ fw1, const float* __restrict__ fb1) {
    __shared__ float s1s[32], t1s[32], s2s[32], t2s[32], xm[32];
    int t = threadIdx.x;
    if (t < 32) {
        s1s[t] = d_prep[t]; t1s[t] = d_prep[32 + t];
        float mu = d_small[96 + t] * (1.f / NNODES);
        float var = d_small[128 + t] * (1.f / NNODES) - mu * mu;
        float s = g2[t] * rsqrtf(var + 1e-5f);
        s2s[t] = s; t2s[t] = be2[t] - mu * s;
        xm[t] = d_small[t] * (1.f / NNODES);
    }
    __syncthreads();
    for (int i = t; i < 3072; i += 128) {
        int r = i >> 5, k = i & 31;
        int j = (r < 32) ? r : r + 32;
        d_prep2[i]        = s1s[k] * wih1[j * 64 + k];
        d_prep2[3072 + i] = s2s[k] * wih1[j * 64 + 32 + k];
        d_prep2[6144 + i] = wih2[j * 32 + k];
    }
    for (int r = t; r < 96; r += 128) {
        int j = (r < 32) ? r : r + 32;
        float g = bih1[j] + bhh1[j];
        for (int k = 0; k < 32; k++)
            g += t1s[k] * wih1[j * 64 + k] + t2s[k] * wih1[j * 64 + 32 + k];
        d_prep2[9216 + r] = g;
        d_prep2[9312 + r] = bih2[j] + bhh2[j];
    }
    for (int o = t; o < 32; o += 128) {
        float v = fb1[o];
        for (int k = 0; k < 32; k++) v += fw1[o * 96 + 64 + k] * xm[k];
        d_prep2[9408 + o] = v;
    }
}

// fused tail with packed f32x2 math; weight operands loaded as LDS.128 pairs.
__global__ __launch_bounds__(128) void k_final(const float* __restrict__ fw1,
                                               const float* __restrict__ fw2,
                                               const float* __restrict__ fb2,
                                               float* __restrict__ out) {
    __shared__ ull sA1p[1536], sA2p[1536], sW2p[1536], sF1p[1024];
    __shared__ float sGb1[96], sGb2[96], sFb1p[32], sFw2[32];
    __shared__ float sFb2v;
    int t = threadIdx.x;
    {
        float* fA1 = (float*)sA1p; float* fA2 = (float*)sA2p;
        float* fW2 = (float*)sW2p; float* fF1 = (float*)sF1p;
        for (int i = t; i < 3072; i += 128) {
            fA1[i] = d_prep2[i];
            fA2[i] = d_prep2[3072 + i];
            fW2[i] = d_prep2[6144 + i];
        }
        for (int i = t; i < 2048; i += 128) {
            int o = i >> 6, k = i & 63;
            fF1[i] = fw1[o * 96 + k];
        }
    }
    if (t < 96) { sGb1[t] = d_prep2[9216 + t]; sGb2[t] = d_prep2[9312 + t]; }
    if (t < 32) { sFb1p[t] = d_prep2[9408 + t]; sFw2[t] = fw2[t]; }
    if (t == 0) sFb2v = fb2[0];
    __syncthreads();

    int node = blockIdx.x * 128 + t;
    if (node >= NNODES) return;

    const ulonglong2* A1q = reinterpret_cast<const ulonglong2*>(sA1p);
    const ulonglong2* A2q = reinterpret_cast<const ulonglong2*>(sA2p);
    const ulonglong2* W2q = reinterpret_cast<const ulonglong2*>(sW2p);
    const ulonglong2* F1q = reinterpret_cast<const ulonglong2*>(sF1p);

    ull r1p[16], r2p[16];
    {
        const ulonglong2* q1 = reinterpret_cast<const ulonglong2*>(d_r1 + node * 32);
        const ulonglong2* q2 = reinterpret_cast<const ulonglong2*>(d_r2 + node * 32);
#pragma unroll
        for (int c = 0; c < 8; c++) {
            ulonglong2 a = q1[c]; r1p[2*c] = a.x; r1p[2*c+1] = a.y;
            ulonglong2 b = q2[c]; r2p[2*c] = b.x; r2p[2*c+1] = b.y;
        }
    }

    float hn1[32];
#pragma unroll
    for (int h = 0; h < 32; h++) {
        ull ai = pack2(sGb1[h], 0.f);
        ull ag = pack2(sGb1[32 + h], 0.f);
        ull ao = pack2(sGb1[64 + h], 0.f);
#pragma unroll
        for (int p = 0; p < 8; p++) {           // k2 = 2p, 2p+1 via LDS.128
            ulonglong2 wa1i = A1q[h * 8 + p];
            ulonglong2 wa2i = A2q[h * 8 + p];
            ulonglong2 wa1g = A1q[(32 + h) * 8 + p];
            ulonglong2 wa2g = A2q[(32 + h) * 8 + p];
            ulonglong2 wa1o = A1q[(64 + h) * 8 + p];
            ulonglong2 wa2o = A2q[(64 + h) * 8 + p];
            FMA2(ai, r1p[2*p],     wa1i.x, ai);
            FMA2(ai, r1p[2*p + 1], wa1i.y, ai);
            FMA2(ai, r2p[2*p],     wa2i.x, ai);
            FMA2(ai, r2p[2*p + 1], wa2i.y, ai);
            FMA2(ag, r1p[2*p],     wa1g.x, ag);
            FMA2(ag, r1p[2*p + 1], wa1g.y, ag);
            FMA2(ag, r2p[2*p],     wa2g.x, ag);
            FMA2(ag, r2p[2*p + 1], wa2g.y, ag);
            FMA2(ao, r1p[2*p],     wa1o.x, ao);
            FMA2(ao, r1p[2*p + 1], wa1o.y, ao);
            FMA2(ao, r2p[2*p],     wa2o.x, ao);
            FMA2(ao, r2p[2*p + 1], wa2o.y, ao);
        }
        float l0, l1, gi, gg, go;
        unpack2(ai, l0, l1); gi = l0 + l1;
        unpack2(ag, l0, l1); gg = l0 + l1;
        unpack2(ao, l0, l1); go = l0 + l1;
        float c = fsig(gi) * ftanh_(gg);
        hn1[h] = fsig(go) * ftanh_(c);
    }
    ull hn1p[16];
#pragma unroll
    for (int k2 = 0; k2 < 16; k2++) hn1p[k2] = pack2(hn1[2*k2], hn1[2*k2+1]);

    float hn2[32];
#pragma unroll
    for (int h = 0; h < 32; h++) {
        ull ai = pack2(sGb2[h], 0.f);
        ull ag = pack2(sGb2[32 + h], 0.f);
        ull ao = pack2(sGb2[64 + h], 0.f);
#pragma unroll
        for (int p = 0; p < 8; p++) {
            ulonglong2 wi = W2q[h * 8 + p];
            ulonglong2 wg = W2q[(32 + h) * 8 + p];
            ulonglong2 wo = W2q[(64 + h) * 8 + p];
            FMA2(ai, hn1p[2*p],     wi.x, ai);
            FMA2(ai, hn1p[2*p + 1], wi.y, ai);
            FMA2(ag, hn1p[2*p],     wg.x, ag);
            FMA2(ag, hn1p[2*p + 1], wg.y, ag);
            FMA2(ao, hn1p[2*p],     wo.x, ao);
            FMA2(ao, hn1p[2*p + 1], wo.y, ao);
        }
        float l0, l1, gi, gg, go;
        unpack2(ai, l0, l1); gi = l0 + l1;
        unpack2(ag, l0, l1); gg = l0 + l1;
        unpack2(ao, l0, l1); go = l0 + l1;
        float c = fsig(gi) * ftanh_(gg);
        hn2[h] = fsig(go) * ftanh_(c);
    }
    ull hn2p[16];
#pragma unroll
    for (int k2 = 0; k2 < 16; k2++) hn2p[k2] = pack2(hn2[2*k2], hn2[2*k2+1]);

    float acc = sFb2v;
#pragma unroll
    for (int o = 0; o < 32; o++) {
        ull a2 = pack2(sFb1p[o], 0.f);
#pragma unroll
        for (int p = 0; p < 8; p++) {
            ulonglong2 w1 = F1q[o * 16 + p];        // hn1 block
            ulonglong2 w2v = F1q[o * 16 + 8 + p];   // hn2 block
            FMA2(a2, hn1p[2*p],     w1.x, a2);
            FMA2(a2, hn1p[2*p + 1], w1.y, a2);
            FMA2(a2, hn2p[2*p],     w2v.x, a2);
            FMA2(a2, hn2p[2*p + 1], w2v.y, a2);
        }
        float l0, l1;
        unpack2(a2, l0, l1);
        acc = fmaf(fmaxf(l0 + l1, 0.f), sFw2[o], acc);
    }
    out[node] = acc;
}

// ---------------- launch ----------------
extern "C" void kernel_launch(void* const* d_in, const int* in_sizes, int n_in,
                              void* d_out, int out_size) {
    const float* x    = (const float*)d_in[0];
    const int*   ei   = (const int*)d_in[1];
    const float* ea   = (const float*)d_in[2];
    const float* w1   = (const float*)d_in[3];
    const float* b1   = (const float*)d_in[4];
    const float* g1   = (const float*)d_in[5];
    const float* be1  = (const float*)d_in[6];
    const float* w2   = (const float*)d_in[7];
    const float* b2   = (const float*)d_in[8];
    const float* g2   = (const float*)d_in[9];
    const float* be2  = (const float*)d_in[10];
    const float* wih1 = (const float*)d_in[11];
    const float* bih1 = (const float*)d_in[13];
    const float* bhh1 = (const float*)d_in[14];
    const float* wih2 = (const float*)d_in[15];
    const float* bih2 = (const float*)d_in[17];
    const float* bhh2 = (const float*)d_in[18];
    const float* fw1  = (const float*)d_in[19];
    const float* fb1  = (const float*)d_in[20];
    const float* fw2  = (const float*)d_in[21];
    const float* fb2  = (const float*)d_in[22];
    float* out = (float*)d_out;

    const int* src = ei;
    const int* dst = ei + NEDGES;

    const int NB_N  = (NNODES + 255) / 256;            // 391
    const int NB_Q  = (NEDGES / 4 + 255) / 256;        // 1563
    const int NB_E8 = (NEDGES / 4 * 8 + 255) / 256;    // 12500
    const int NB_G  = (NNODES + 127) / 128;            // 782 (gemm, 128-thread blocks)
    const int NB_F  = (NNODES + 127) / 128;            // 782
    const int NB_S  = 148;

    k_zero_all<<<NB_N, 256>>>();
    k_deg<<<NB_Q, 256>>>(dst, ea);
    k_colsum<<<NB_S, 256>>>(x);   // includes fused nodeprep (dinv)

    // GCN layer 1
    k_gemm<1><<<NB_G, 128>>>(x, w1);
    k_edge<<<NB_E8, 256>>>(src, dst, ea);
    k_post<1><<<NB_S * 2, 256>>>(b1);

    // fold BN1 into layer-2 weights; GCN layer 2
    k_prep1<<<1, 32>>>(g1, be1, w2);
    k_gemm<2><<<NB_G, 128>>>(nullptr, nullptr);
    k_edge<<<NB_E8, 256>>>(src, dst, ea);
    k_post<2><<<NB_S * 2, 256>>>(b2);

    // fold BN1/BN2 into LSTM1, skip_avg into fc1 bias; fused tail
    k_prep2<<<1, 128>>>(g2, be2, wih1, bih1, bhh1, wih2, bih2, bhh2, fw1, fb1);
    k_final<<<NB_F, 128>>>(fw1, fw2, fb2, out);
}

// round 14
// speedup vs baseline: 1.0061x; 1.0061x over previous
#include <cuda_runtime.h>

#define NNODES 100000
#define NEDGES 1600000
typedef unsigned long long ull;

// ---------------- scratch (device globals; no allocation) ----------------
__device__ float d_xw[NNODES*32];    // xws = (X@W)*dinv of current GCN layer
__device__ float d_agg[NNODES*32];   // edge aggregation accumulator (reused)
__device__ float d_r1[NNODES*32];    // relu(gcn1) pre-BN
__device__ float d_r2[NNODES*32];    // relu(gcn2) pre-BN
__device__ float d_deg[NNODES];
__device__ float d_dinv[NNODES];
__device__ int   d_ctr[2];           // last-block counters (self-resetting)
// d_small: [0:32) xsum, [32:64) sum1, [64:96) sq1, [96:128) sum2, [128:160) sq2
__device__ float d_small[160];
// d_prep: [0:32) s1, [32:64) t1, [64:1088) w2p (=diag(s1)@w2), [1088:1120) c2 (=t1@w2)
__device__ float d_prep[1120];
// d_prep2: A1c[3072], A2c[3072], W2c[3072], gb1c[96], gb2c[96], fb1p[32]
__device__ float d_prep2[9440];

// ---------------- helpers ----------------
__device__ __forceinline__ void red_add_v4(float* addr, float a, float b, float c, float d) {
    asm volatile("red.global.add.v4.f32 [%0], {%1,%2,%3,%4};"
                 :: "l"(addr), "f"(a), "f"(b), "f"(c), "f"(d) : "memory");
}
__device__ __forceinline__ float fsig(float x) {
    return __fdividef(1.f, 1.f + __expf(-x));
}
__device__ __forceinline__ float ftanh_(float x) {
    x = fminf(fmaxf(x, -15.f), 15.f);
    float e = __expf(2.f * x);
    return __fdividef(e - 1.f, e + 1.f);
}
#define FMA2(d, a, b, c) asm("fma.rn.f32x2 %0, %1, %2, %3;" : "=l"(d) : "l"(a), "l"(b), "l"(c))
#define MUL2(d, a, b)    asm("mul.rn.f32x2 %0, %1, %2;" : "=l"(d) : "l"(a), "l"(b))
__device__ __forceinline__ ull pack2(float lo, float hi) {
    ull r; asm("mov.b64 %0, {%1, %2};" : "=l"(r) : "f"(lo), "f"(hi)); return r;
}
__device__ __forceinline__ void unpack2(ull v, float& lo, float& hi) {
    asm("mov.b64 {%0, %1}, %2;" : "=f"(lo), "=f"(hi) : "l"(v));
}

// ---------------- kernels ----------------
// tiny init: deg + stat slots only (agg zeroing moved to k_colsum)
__global__ void k_zero_all() {
    int i = blockIdx.x * blockDim.x + threadIdx.x;
    if (i < NNODES) d_deg[i] = 0.f;
    if (i < 160) d_small[i] = 0.f;
}

// weighted in-degree: 4 edges per thread, vectorized index loads
__global__ void k_deg(const int* __restrict__ dst, const float* __restrict__ ea) {
    int q = blockIdx.x * blockDim.x + threadIdx.x;
    if (q >= NEDGES / 4) return;
    int4 d4 = __ldg(reinterpret_cast<const int4*>(dst) + q);
    float4 a4 = __ldg(reinterpret_cast<const float4*>(ea) + q);
    atomicAdd(&d_deg[d4.x], a4.x);
    atomicAdd(&d_deg[d4.y], a4.y);
    atomicAdd(&d_deg[d4.z], a4.z);
    atomicAdd(&d_deg[d4.w], a4.w);
}

// column sums of x + fused nodeprep (dinv) + d_agg zeroing; runs after k_deg.
__global__ void k_colsum(const float* __restrict__ x) {
    int t = blockIdx.x * blockDim.x + threadIdx.x;
    int stride = gridDim.x * blockDim.x;
    float4 acc = make_float4(0.f, 0.f, 0.f, 0.f);
    const float4* x4 = reinterpret_cast<const float4*>(x);
    float4* A4 = reinterpret_cast<float4*>(d_agg);
    float4 z = make_float4(0.f, 0.f, 0.f, 0.f);
    for (int i = t; i < NNODES * 8; i += stride) {
        float4 v = __ldg(x4 + i);
        acc.x += v.x; acc.y += v.y; acc.z += v.z; acc.w += v.w;
        A4[i] = z;
    }
#pragma unroll
    for (int o = 8; o < 32; o <<= 1) {
        acc.x += __shfl_xor_sync(0xffffffffu, acc.x, o);
        acc.y += __shfl_xor_sync(0xffffffffu, acc.y, o);
        acc.z += __shfl_xor_sync(0xffffffffu, acc.z, o);
        acc.w += __shfl_xor_sync(0xffffffffu, acc.w, o);
    }
    int lane = threadIdx.x & 31;
    if (lane < 8) {
        int g = (t & 7) * 4;
        atomicAdd(&d_small[g + 0], acc.x);
        atomicAdd(&d_small[g + 1], acc.y);
        atomicAdd(&d_small[g + 2], acc.z);
        atomicAdd(&d_small[g + 3], acc.w);
    }
    // fused nodeprep: dinv = rsqrt(deg + 1)
    for (int i = t; i < NNODES; i += stride)
        d_dinv[i] = rsqrtf(d_deg[i] + 1.f);
}

// xws = (X @ W (+rowbias)) * dinv[node], f32x2 packed over output-feature pairs.
template<int L>
__global__ void k_gemm(const float* __restrict__ Xin, const float* __restrict__ Win) {
    __shared__ float xs[256 * 33];
    __shared__ float ws[1024];
    __shared__ float bs[32];
    int t = threadIdx.x;
    int base = blockIdx.x * 256;
    const float* X = (L == 1) ? Xin : d_r1;
    const float* W = (L == 1) ? Win : (d_prep + 64);
    for (int i = t; i < 1024; i += 256) ws[i] = W[i];
    if (t < 32) bs[t] = (L == 1) ? 0.f : d_prep[1088 + t];
    for (int i = t; i < 8192; i += 256) {
        int g = base * 32 + i;
        xs[(i >> 5) * 33 + (i & 31)] = (g < NNODES * 32) ? X[g] : 0.f;
    }
    __syncthreads();
    int node = base + t;
    if (node >= NNODES) return;
    ull out2[16];
    const ull* bs2 = reinterpret_cast<const ull*>(bs);
#pragma unroll
    for (int h2 = 0; h2 < 16; h2++) out2[h2] = bs2[h2];
#pragma unroll
    for (int k = 0; k < 32; k++) {
        float xv = xs[t * 33 + k];
        ull xv2 = pack2(xv, xv);
        const ull* wrow = reinterpret_cast<const ull*>(ws + k * 32);
#pragma unroll
        for (int h2 = 0; h2 < 16; h2++)
            FMA2(out2[h2], xv2, wrow[h2], out2[h2]);
    }
    float dv = __ldg(&d_dinv[node]);
    ull dv2 = pack2(dv, dv);
#pragma unroll
    for (int h2 = 0; h2 < 16; h2++) MUL2(out2[h2], out2[h2], dv2);
    ulonglong2* o2 = reinterpret_cast<ulonglong2*>(d_xw + node * 32);
#pragma unroll
    for (int c = 0; c < 8; c++)
        o2[c] = make_ulonglong2(out2[2*c], out2[2*c+1]);
}

// scatter: group of 8 lanes handles 4 edges; lane's chunk c = t&7.
__global__ void k_edge(const int* __restrict__ src, const int* __restrict__ dst,
                       const float* __restrict__ ea) {
    int t = blockIdx.x * blockDim.x + threadIdx.x;
    int g = t >> 3;                 // edge-quad index
    int c = t & 7;                  // float4 chunk within feature row
    if (g >= NEDGES / 4) return;
    int4 s4 = __ldg(reinterpret_cast<const int4*>(src) + g);
    int4 d4 = __ldg(reinterpret_cast<const int4*>(dst) + g);
    float4 a4 = __ldg(reinterpret_cast<const float4*>(ea) + g);
    const float4* X = reinterpret_cast<const float4*>(d_xw);
    float4 v0 = __ldg(X + s4.x * 8 + c);
    float4 v1 = __ldg(X + s4.y * 8 + c);
    float4 v2 = __ldg(X + s4.z * 8 + c);
    float4 v3 = __ldg(X + s4.w * 8 + c);
    red_add_v4(d_agg + d4.x * 32 + c * 4, v0.x * a4.x, v0.y * a4.x, v0.z * a4.x, v0.w * a4.x);
    red_add_v4(d_agg + d4.y * 32 + c * 4, v1.x * a4.y, v1.y * a4.y, v1.z * a4.y, v1.w * a4.y);
    red_add_v4(d_agg + d4.z * 32 + c * 4, v2.x * a4.z, v2.y * a4.z, v2.z * a4.z, v2.w * a4.z);
    red_add_v4(d_agg + d4.w * 32 + c * 4, v3.x * a4.w, v3.y * a4.w, v3.z * a4.w, v3.w * a4.w);
}

// r = relu((agg + xws)*dinv + b); BN stats; L==1 re-zeroes agg; last block runs prep.
template<int L>
__global__ void k_post(const float* __restrict__ bias,
                       const float* __restrict__ gam, const float* __restrict__ bet,
                       const float* __restrict__ w2,
                       const float* __restrict__ wih1, const float* __restrict__ bih1,
                       const float* __restrict__ bhh1, const float* __restrict__ wih2,
                       const float* __restrict__ bih2, const float* __restrict__ bhh2,
                       const float* __restrict__ fw1, const float* __restrict__ fb1) {
    int t = threadIdx.x;
    int gt = blockIdx.x * blockDim.x + t;
    int stride = gridDim.x * blockDim.x;
    int g = (gt & 7) * 4;
    float4 bf = *reinterpret_cast<const float4*>(bias + g);
    float* R = (L == 1) ? d_r1 : d_r2;
    float4 s = make_float4(0.f, 0.f, 0.f, 0.f);
    float4 q = make_float4(0.f, 0.f, 0.f, 0.f);
    float4* A4 = reinterpret_cast<float4*>(d_agg);
    const float4* X4 = reinterpret_cast<const float4*>(d_xw);
    float4* R4 = reinterpret_cast<float4*>(R);
    float4 z = make_float4(0.f, 0.f, 0.f, 0.f);
    for (int i = gt; i < NNODES * 8; i += stride) {
        int node = i >> 3;
        float dv = __ldg(d_dinv + node);
        float4 a = A4[i];
        float4 xw = X4[i];
        float4 v;
        v.x = fmaxf((a.x + xw.x) * dv + bf.x, 0.f);
        v.y = fmaxf((a.y + xw.y) * dv + bf.y, 0.f);
        v.z = fmaxf((a.z + xw.z) * dv + bf.z, 0.f);
        v.w = fmaxf((a.w + xw.w) * dv + bf.w, 0.f);
        R4[i] = v;
        if (L == 1) A4[i] = z;   // re-zero accumulator for layer 2
        s.x += v.x; s.y += v.y; s.z += v.z; s.w += v.w;
        q.x = fmaf(v.x, v.x, q.x); q.y = fmaf(v.y, v.y, q.y);
        q.z = fmaf(v.z, v.z, q.z); q.w = fmaf(v.w, v.w, q.w);
    }
#pragma unroll
    for (int o = 8; o < 32; o <<= 1) {
        s.x += __shfl_xor_sync(0xffffffffu, s.x, o);
        s.y += __shfl_xor_sync(0xffffffffu, s.y, o);
        s.z += __shfl_xor_sync(0xffffffffu, s.z, o);
        s.w += __shfl_xor_sync(0xffffffffu, s.w, o);
        q.x += __shfl_xor_sync(0xffffffffu, q.x, o);
        q.y += __shfl_xor_sync(0xffffffffu, q.y, o);
        q.z += __shfl_xor_sync(0xffffffffu, q.z, o);
        q.w += __shfl_xor_sync(0xffffffffu, q.w, o);
    }
    int lane = t & 31;
    if (lane < 8) {
        int off = (L == 1) ? 32 : 96;
        atomicAdd(&d_small[off + g + 0], s.x);
        atomicAdd(&d_small[off + g + 1], s.y);
        atomicAdd(&d_small[off + g + 2], s.z);
        atomicAdd(&d_small[off + g + 3], s.w);
        atomicAdd(&d_small[off + 32 + g + 0], q.x);
        atomicAdd(&d_small[off + 32 + g + 1], q.y);
        atomicAdd(&d_small[off + 32 + g + 2], q.z);
        atomicAdd(&d_small[off + 32 + g + 3], q.w);
    }

    // ---- last-block fused prep ----
    __shared__ bool isLast;
    __syncthreads();
    if (t == 0) {
        __threadfence();
        int prev = atomicAdd(&d_ctr[L - 1], 1);
        isLast = (prev == (int)gridDim.x - 1);
        if (isLast) d_ctr[L - 1] = 0;   // self-reset for next replay
    }
    __syncthreads();
    if (!isLast) return;

    if (L == 1) {
        // prep1: finalize BN1; build w2p = diag(s1)@w2 and c2 = t1@w2
        __shared__ float t1s[32];
        float sc = 0.f, tt = 0.f;
        if (t < 32) {
            float mu = __ldcg(&d_small[32 + t]) * (1.f / NNODES);
            float var = __ldcg(&d_small[64 + t]) * (1.f / NNODES) - mu * mu;
            sc = gam[t] * rsqrtf(var + 1e-5f);
            tt = bet[t] - mu * sc;
            t1s[t] = tt;
            d_prep[t] = sc; d_prep[32 + t] = tt;
        }
        __syncthreads();
        if (t < 32) {
            for (int h = 0; h < 32; h++) d_prep[64 + t * 32 + h] = sc * w2[t * 32 + h];
            float c = 0.f;
            for (int k = 0; k < 32; k++) c += t1s[k] * w2[k * 32 + t];
            d_prep[1088 + t] = c;
        }
    } else {
        // prep2: finalize BN2; fold BN1/BN2 into LSTM1; fold skip_avg into fc1 bias.
        __shared__ float s1s[32], t1s[32], s2s[32], t2s[32], xm[32];
        if (t < 32) {
            s1s[t] = d_prep[t]; t1s[t] = d_prep[32 + t];
            float mu = __ldcg(&d_small[96 + t]) * (1.f / NNODES);
            float var = __ldcg(&d_small[128 + t]) * (1.f / NNODES) - mu * mu;
            float sc = gam[t] * rsqrtf(var + 1e-5f);
            s2s[t] = sc; t2s[t] = bet[t] - mu * sc;
            xm[t] = d_small[t] * (1.f / NNODES);
        }
        __syncthreads();
        for (int i = t; i < 3072; i += 256) {
            int r = i >> 5, k = i & 31;
            int j = (r < 32) ? r : r + 32;
            d_prep2[i]        = s1s[k] * wih1[j * 64 + k];
            d_prep2[3072 + i] = s2s[k] * wih1[j * 64 + 32 + k];
            d_prep2[6144 + i] = wih2[j * 32 + k];
        }
        for (int r = t; r < 96; r += 256) {
            int j = (r < 32) ? r : r + 32;
            float gg = bih1[j] + bhh1[j];
            for (int k = 0; k < 32; k++)
                gg += t1s[k] * wih1[j * 64 + k] + t2s[k] * wih1[j * 64 + 32 + k];
            d_prep2[9216 + r] = gg;
            d_prep2[9312 + r] = bih2[j] + bhh2[j];
        }
        for (int o = t; o < 32; o += 256) {
            float v = fb1[o];
            for (int k = 0; k < 32; k++) v += fw1[o * 96 + 64 + k] * xm[k];
            d_prep2[9408 + o] = v;
        }
    }
}

// fused tail with packed f32x2 math; weight operands loaded as LDS.128 pairs.
__global__ __launch_bounds__(128) void k_final(const float* __restrict__ fw1,
                                               const float* __restrict__ fw2,
                                               const float* __restrict__ fb2,
                                               float* __restrict__ out) {
    __shared__ ull sA1p[1536], sA2p[1536], sW2p[1536], sF1p[1024];
    __shared__ float sGb1[96], sGb2[96], sFb1p[32], sFw2[32];
    __shared__ float sFb2v;
    int t = threadIdx.x;
    {
        float* fA1 = (float*)sA1p; float* fA2 = (float*)sA2p;
        float* fW2 = (float*)sW2p; float* fF1 = (float*)sF1p;
        for (int i = t; i < 3072; i += 128) {
            fA1[i] = d_prep2[i];
            fA2[i] = d_prep2[3072 + i];
            fW2[i] = d_prep2[6144 + i];
        }
        for (int i = t; i < 2048; i += 128) {
            int o = i >> 6, k = i & 63;
            fF1[i] = fw1[o * 96 + k];
        }
    }
    if (t < 96) { sGb1[t] = d_prep2[9216 + t]; sGb2[t] = d_prep2[9312 + t]; }
    if (t < 32) { sFb1p[t] = d_prep2[9408 + t]; sFw2[t] = fw2[t]; }
    if (t == 0) sFb2v = fb2[0];
    __syncthreads();

    int node = blockIdx.x * 128 + t;
    if (node >= NNODES) return;

    const ulonglong2* A1q = reinterpret_cast<const ulonglong2*>(sA1p);
    const ulonglong2* A2q = reinterpret_cast<const ulonglong2*>(sA2p);
    const ulonglong2* W2q = reinterpret_cast<const ulonglong2*>(sW2p);
    const ulonglong2* F1q = reinterpret_cast<const ulonglong2*>(sF1p);

    ull r1p[16], r2p[16];
    {
        const ulonglong2* q1 = reinterpret_cast<const ulonglong2*>(d_r1 + node * 32);
        const ulonglong2* q2 = reinterpret_cast<const ulonglong2*>(d_r2 + node * 32);
#pragma unroll
        for (int c = 0; c < 8; c++) {
            ulonglong2 a = q1[c]; r1p[2*c] = a.x; r1p[2*c+1] = a.y;
            ulonglong2 b = q2[c]; r2p[2*c] = b.x; r2p[2*c+1] = b.y;
        }
    }

    float hn1[32];
#pragma unroll
    for (int h = 0; h < 32; h++) {
        ull ai = pack2(sGb1[h], 0.f);
        ull ag = pack2(sGb1[32 + h], 0.f);
        ull ao = pack2(sGb1[64 + h], 0.f);
#pragma unroll
        for (int p = 0; p < 8; p++) {
            ulonglong2 wa1i = A1q[h * 8 + p];
            ulonglong2 wa2i = A2q[h * 8 + p];
            ulonglong2 wa1g = A1q[(32 + h) * 8 + p];
            ulonglong2 wa2g = A2q[(32 + h) * 8 + p];
            ulonglong2 wa1o = A1q[(64 + h) * 8 + p];
            ulonglong2 wa2o = A2q[(64 + h) * 8 + p];
            FMA2(ai, r1p[2*p],     wa1i.x, ai);
            FMA2(ai, r1p[2*p + 1], wa1i.y, ai);
            FMA2(ai, r2p[2*p],     wa2i.x, ai);
            FMA2(ai, r2p[2*p + 1], wa2i.y, ai);
            FMA2(ag, r1p[2*p],     wa1g.x, ag);
            FMA2(ag, r1p[2*p + 1], wa1g.y, ag);
            FMA2(ag, r2p[2*p],     wa2g.x, ag);
            FMA2(ag, r2p[2*p + 1], wa2g.y, ag);
            FMA2(ao, r1p[2*p],     wa1o.x, ao);
            FMA2(ao, r1p[2*p + 1], wa1o.y, ao);
            FMA2(ao, r2p[2*p],     wa2o.x, ao);
            FMA2(ao, r2p[2*p + 1], wa2o.y, ao);
        }
        float l0, l1, gi, gg, go;
        unpack2(ai, l0, l1); gi = l0 + l1;
        unpack2(ag, l0, l1); gg = l0 + l1;
        unpack2(ao, l0, l1); go = l0 + l1;
        float c = fsig(gi) * ftanh_(gg);
        hn1[h] = fsig(go) * ftanh_(c);
    }
    ull hn1p[16];
#pragma unroll
    for (int k2 = 0; k2 < 16; k2++) hn1p[k2] = pack2(hn1[2*k2], hn1[2*k2+1]);

    float hn2[32];
#pragma unroll
    for (int h = 0; h < 32; h++) {
        ull ai = pack2(sGb2[h], 0.f);
        ull ag = pack2(sGb2[32 + h], 0.f);
        ull ao = pack2(sGb2[64 + h], 0.f);
#pragma unroll
        for (int p = 0; p < 8; p++) {
            ulonglong2 wi = W2q[h * 8 + p];
            ulonglong2 wg = W2q[(32 + h) * 8 + p];
            ulonglong2 wo = W2q[(64 + h) * 8 + p];
            FMA2(ai, hn1p[2*p],     wi.x, ai);
            FMA2(ai, hn1p[2*p + 1], wi.y, ai);
            FMA2(ag, hn1p[2*p],     wg.x, ag);
            FMA2(ag, hn1p[2*p + 1], wg.y, ag);
            FMA2(ao, hn1p[2*p],     wo.x, ao);
            FMA2(ao, hn1p[2*p + 1], wo.y, ao);
        }
        float l0, l1, gi, gg, go;
        unpack2(ai, l0, l1); gi = l0 + l1;
        unpack2(ag, l0, l1); gg = l0 + l1;
        unpack2(ao, l0, l1); go = l0 + l1;
        float c = fsig(gi) * ftanh_(gg);
        hn2[h] = fsig(go) * ftanh_(c);
    }
    ull hn2p[16];
#pragma unroll
    for (int k2 = 0; k2 < 16; k2++) hn2p[k2] = pack2(hn2[2*k2], hn2[2*k2+1]);

    float acc = sFb2v;
#pragma unroll
    for (int o = 0; o < 32; o++) {
        ull a2 = pack2(sFb1p[o], 0.f);
#pragma unroll
        for (int p = 0; p < 8; p++) {
            ulonglong2 w1 = F1q[o * 16 + p];
            ulonglong2 w2v = F1q[o * 16 + 8 + p];
            FMA2(a2, hn1p[2*p],     w1.x, a2);
            FMA2(a2, hn1p[2*p + 1], w1.y, a2);
            FMA2(a2, hn2p[2*p],     w2v.x, a2);
            FMA2(a2, hn2p[2*p + 1], w2v.y, a2);
        }
        float l0, l1;
        unpack2(a2, l0, l1);
        acc = fmaf(fmaxf(l0 + l1, 0.f), sFw2[o], acc);
    }
    out[node] = acc;
}

// ---------------- launch ----------------
extern "C" void kernel_launch(void* const* d_in, const int* in_sizes, int n_in,
                              void* d_out, int out_size) {
    const float* x    = (const float*)d_in[0];
    const int*   ei   = (const int*)d_in[1];
    const float* ea   = (const float*)d_in[2];
    const float* w1   = (const float*)d_in[3];
    const float* b1   = (const float*)d_in[4];
    const float* g1   = (const float*)d_in[5];
    const float* be1  = (const float*)d_in[6];
    const float* w2   = (const float*)d_in[7];
    const float* b2   = (const float*)d_in[8];
    const float* g2   = (const float*)d_in[9];
    const float* be2  = (const float*)d_in[10];
    const float* wih1 = (const float*)d_in[11];
    const float* bih1 = (const float*)d_in[13];
    const float* bhh1 = (const float*)d_in[14];
    const float* wih2 = (const float*)d_in[15];
    const float* bih2 = (const float*)d_in[17];
    const float* bhh2 = (const float*)d_in[18];
    const float* fw1  = (const float*)d_in[19];
    const float* fb1  = (const float*)d_in[20];
    const float* fw2  = (const float*)d_in[21];
    const float* fb2  = (const float*)d_in[22];
    float* out = (float*)d_out;

    const int* src = ei;
    const int* dst = ei + NEDGES;

    const int NB_N  = (NNODES + 255) / 256;            // 391
    const int NB_Q  = (NEDGES / 4 + 255) / 256;        // 1563
    const int NB_E8 = (NEDGES / 4 * 8 + 255) / 256;    // 12500
    const int NB_G  = (NNODES + 255) / 256;            // 391 (gemm, 256-thread blocks)
    const int NB_F  = (NNODES + 127) / 128;            // 782
    const int NB_S  = 148;

    k_zero_all<<<NB_N, 256>>>();
    k_deg<<<NB_Q, 256>>>(dst, ea);
    k_colsum<<<NB_S, 256>>>(x);   // + fused nodeprep + agg zeroing

    // GCN layer 1
    k_gemm<1><<<NB_G, 256>>>(x, w1);
    k_edge<<<NB_E8, 256>>>(src, dst, ea);
    k_post<1><<<NB_S * 2, 256>>>(b1, g1, be1, w2,
                                 nullptr, nullptr, nullptr, nullptr,
                                 nullptr, nullptr, nullptr, nullptr);  // fused prep1

    // GCN layer 2
    k_gemm<2><<<NB_G, 256>>>(nullptr, nullptr);
    k_edge<<<NB_E8, 256>>>(src, dst, ea);
    k_post<2><<<NB_S * 2, 256>>>(b2, g2, be2, nullptr,
                                 wih1, bih1, bhh1, wih2,
                                 bih2, bhh2, fw1, fb1);                // fused prep2

    // fused tail
    k_final<<<NB_F, 128>>>(fw1, fw2, fb2, out);
}

// round 15
// speedup vs baseline: 1.0189x; 1.0127x over previous
#include <cuda_runtime.h>

#define NNODES 100000
#define NEDGES 1600000
typedef unsigned long long ull;

// ---------------- scratch (device globals; no allocation) ----------------
__device__ float d_xw[NNODES*32];    // xws = (X@W)*dinv of current GCN layer
__device__ float d_agg[NNODES*32];   // edge aggregation accumulator (reused)
__device__ float d_r1[NNODES*32];    // relu(gcn1) pre-BN
__device__ float d_r2[NNODES*32];    // relu(gcn2) pre-BN
__device__ float d_deg[NNODES];
__device__ float d_dinv[NNODES];
__device__ int   d_ctr[2];           // last-block counters (self-resetting)
// d_small: [0:32) xsum, [32:64) sum1, [64:96) sq1, [96:128) sum2, [128:160) sq2
__device__ float d_small[160];
// d_prep: [0:32) s1, [32:64) t1, [64:1088) w2p (=diag(s1)@w2), [1088:1120) c2 (=t1@w2)
__device__ float d_prep[1120];
// d_prep2: A1c[3072], A2c[3072], W2c[3072], gb1c[96], gb2c[96], fb1p[32]
__device__ float d_prep2[9440];

// ---------------- helpers ----------------
__device__ __forceinline__ void red_add_v4(float* addr, float a, float b, float c, float d) {
    asm volatile("red.global.add.v4.f32 [%0], {%1,%2,%3,%4};"
                 :: "l"(addr), "f"(a), "f"(b), "f"(c), "f"(d) : "memory");
}
__device__ __forceinline__ float fsig(float x) {
    return __fdividef(1.f, 1.f + __expf(-x));
}
__device__ __forceinline__ float ftanh_(float x) {
    x = fminf(fmaxf(x, -15.f), 15.f);
    float e = __expf(2.f * x);
    return __fdividef(e - 1.f, e + 1.f);
}
#define FMA2(d, a, b, c) asm("fma.rn.f32x2 %0, %1, %2, %3;" : "=l"(d) : "l"(a), "l"(b), "l"(c))
#define MUL2(d, a, b)    asm("mul.rn.f32x2 %0, %1, %2;" : "=l"(d) : "l"(a), "l"(b))
__device__ __forceinline__ ull pack2(float lo, float hi) {
    ull r; asm("mov.b64 %0, {%1, %2};" : "=l"(r) : "f"(lo), "f"(hi)); return r;
}
__device__ __forceinline__ void unpack2(ull v, float& lo, float& hi) {
    asm("mov.b64 {%0, %1}, %2;" : "=f"(lo), "=f"(hi) : "l"(v));
}

// ---------------- kernels ----------------
// tiny init: deg + stat slots only (agg zeroing moved to k_colsum)
__global__ void k_zero_all() {
    int i = blockIdx.x * blockDim.x + threadIdx.x;
    if (i < NNODES) d_deg[i] = 0.f;
    if (i < 160) d_small[i] = 0.f;
}

// weighted in-degree: 4 edges per thread, vectorized index loads
__global__ void k_deg(const int* __restrict__ dst, const float* __restrict__ ea) {
    int q = blockIdx.x * blockDim.x + threadIdx.x;
    if (q >= NEDGES / 4) return;
    int4 d4 = __ldg(reinterpret_cast<const int4*>(dst) + q);
    float4 a4 = __ldg(reinterpret_cast<const float4*>(ea) + q);
    atomicAdd(&d_deg[d4.x], a4.x);
    atomicAdd(&d_deg[d4.y], a4.y);
    atomicAdd(&d_deg[d4.z], a4.z);
    atomicAdd(&d_deg[d4.w], a4.w);
}

// column sums of x + fused nodeprep (dinv) + d_agg zeroing; runs after k_deg.
__global__ void k_colsum(const float* __restrict__ x) {
    int t = blockIdx.x * blockDim.x + threadIdx.x;
    int stride = gridDim.x * blockDim.x;
    float4 acc = make_float4(0.f, 0.f, 0.f, 0.f);
    const float4* x4 = reinterpret_cast<const float4*>(x);
    float4* A4 = reinterpret_cast<float4*>(d_agg);
    float4 z = make_float4(0.f, 0.f, 0.f, 0.f);
    for (int i = t; i < NNODES * 8; i += stride) {
        float4 v = __ldg(x4 + i);
        acc.x += v.x; acc.y += v.y; acc.z += v.z; acc.w += v.w;
        A4[i] = z;
    }
#pragma unroll
    for (int o = 8; o < 32; o <<= 1) {
        acc.x += __shfl_xor_sync(0xffffffffu, acc.x, o);
        acc.y += __shfl_xor_sync(0xffffffffu, acc.y, o);
        acc.z += __shfl_xor_sync(0xffffffffu, acc.z, o);
        acc.w += __shfl_xor_sync(0xffffffffu, acc.w, o);
    }
    int lane = threadIdx.x & 31;
    if (lane < 8) {
        int g = (t & 7) * 4;
        atomicAdd(&d_small[g + 0], acc.x);
        atomicAdd(&d_small[g + 1], acc.y);
        atomicAdd(&d_small[g + 2], acc.z);
        atomicAdd(&d_small[g + 3], acc.w);
    }
    // fused nodeprep: dinv = rsqrt(deg + 1)
    for (int i = t; i < NNODES; i += stride)
        d_dinv[i] = rsqrtf(d_deg[i] + 1.f);
}

// xws = (X @ W (+rowbias)) * dinv[node], f32x2 packed; weight rows read as LDS.128.
template<int L>
__global__ void k_gemm(const float* __restrict__ Xin, const float* __restrict__ Win) {
    __shared__ __align__(16) float xs[256 * 33];
    __shared__ __align__(16) float ws[1024];
    __shared__ __align__(16) float bs[32];
    int t = threadIdx.x;
    int base = blockIdx.x * 256;
    const float* X = (L == 1) ? Xin : d_r1;
    const float* W = (L == 1) ? Win : (d_prep + 64);
    for (int i = t; i < 1024; i += 256) ws[i] = W[i];
    if (t < 32) bs[t] = (L == 1) ? 0.f : d_prep[1088 + t];
    for (int i = t; i < 8192; i += 256) {
        int g = base * 32 + i;
        xs[(i >> 5) * 33 + (i & 31)] = (g < NNODES * 32) ? X[g] : 0.f;
    }
    __syncthreads();
    int node = base + t;
    if (node >= NNODES) return;
    ull out2[16];
    const ull* bs2 = reinterpret_cast<const ull*>(bs);
#pragma unroll
    for (int h2 = 0; h2 < 16; h2++) out2[h2] = bs2[h2];
    const ulonglong2* ws2 = reinterpret_cast<const ulonglong2*>(ws);
#pragma unroll
    for (int k = 0; k < 32; k++) {
        float xv = xs[t * 33 + k];
        ull xv2 = pack2(xv, xv);
#pragma unroll
        for (int p = 0; p < 8; p++) {
            ulonglong2 w = ws2[k * 8 + p];   // LDS.128: two f32x2 weight pairs
            FMA2(out2[2*p],     xv2, w.x, out2[2*p]);
            FMA2(out2[2*p + 1], xv2, w.y, out2[2*p + 1]);
        }
    }
    float dv = __ldg(&d_dinv[node]);
    ull dv2 = pack2(dv, dv);
#pragma unroll
    for (int h2 = 0; h2 < 16; h2++) MUL2(out2[h2], out2[h2], dv2);
    ulonglong2* o2 = reinterpret_cast<ulonglong2*>(d_xw + node * 32);
#pragma unroll
    for (int c = 0; c < 8; c++)
        o2[c] = make_ulonglong2(out2[2*c], out2[2*c+1]);
}

// scatter: group of 8 lanes handles 4 edges; lane's chunk c = t&7.
__global__ void k_edge(const int* __restrict__ src, const int* __restrict__ dst,
                       const float* __restrict__ ea) {
    int t = blockIdx.x * blockDim.x + threadIdx.x;
    int g = t >> 3;                 // edge-quad index
    int c = t & 7;                  // float4 chunk within feature row
    if (g >= NEDGES / 4) return;
    int4 s4 = __ldg(reinterpret_cast<const int4*>(src) + g);
    int4 d4 = __ldg(reinterpret_cast<const int4*>(dst) + g);
    float4 a4 = __ldg(reinterpret_cast<const float4*>(ea) + g);
    const float4* X = reinterpret_cast<const float4*>(d_xw);
    float4 v0 = __ldg(X + s4.x * 8 + c);
    float4 v1 = __ldg(X + s4.y * 8 + c);
    float4 v2 = __ldg(X + s4.z * 8 + c);
    float4 v3 = __ldg(X + s4.w * 8 + c);
    red_add_v4(d_agg + d4.x * 32 + c * 4, v0.x * a4.x, v0.y * a4.x, v0.z * a4.x, v0.w * a4.x);
    red_add_v4(d_agg + d4.y * 32 + c * 4, v1.x * a4.y, v1.y * a4.y, v1.z * a4.y, v1.w * a4.y);
    red_add_v4(d_agg + d4.z * 32 + c * 4, v2.x * a4.z, v2.y * a4.z, v2.z * a4.z, v2.w * a4.z);
    red_add_v4(d_agg + d4.w * 32 + c * 4, v3.x * a4.w, v3.y * a4.w, v3.z * a4.w, v3.w * a4.w);
}

// r = relu((agg + xws)*dinv + b); BN stats; L==1 re-zeroes agg; last block runs prep.
template<int L>
__global__ void k_post(const float* __restrict__ bias,
                       const float* __restrict__ gam, const float* __restrict__ bet,
                       const float* __restrict__ w2,
                       const float* __restrict__ wih1, const float* __restrict__ bih1,
                       const float* __restrict__ bhh1, const float* __restrict__ wih2,
                       const float* __restrict__ bih2, const float* __restrict__ bhh2,
                       const float* __restrict__ fw1, const float* __restrict__ fb1) {
    int t = threadIdx.x;
    int gt = blockIdx.x * blockDim.x + t;
    int stride = gridDim.x * blockDim.x;
    int g = (gt & 7) * 4;
    float4 bf = *reinterpret_cast<const float4*>(bias + g);
    float* R = (L == 1) ? d_r1 : d_r2;
    float4 s = make_float4(0.f, 0.f, 0.f, 0.f);
    float4 q = make_float4(0.f, 0.f, 0.f, 0.f);
    float4* A4 = reinterpret_cast<float4*>(d_agg);
    const float4* X4 = reinterpret_cast<const float4*>(d_xw);
    float4* R4 = reinterpret_cast<float4*>(R);
    float4 z = make_float4(0.f, 0.f, 0.f, 0.f);
    for (int i = gt; i < NNODES * 8; i += stride) {
        int node = i >> 3;
        float dv = __ldg(d_dinv + node);
        float4 a = A4[i];
        float4 xw = X4[i];
        float4 v;
        v.x = fmaxf((a.x + xw.x) * dv + bf.x, 0.f);
        v.y = fmaxf((a.y + xw.y) * dv + bf.y, 0.f);
        v.z = fmaxf((a.z + xw.z) * dv + bf.z, 0.f);
        v.w = fmaxf((a.w + xw.w) * dv + bf.w, 0.f);
        R4[i] = v;
        if (L == 1) A4[i] = z;   // re-zero accumulator for layer 2
        s.x += v.x; s.y += v.y; s.z += v.z; s.w += v.w;
        q.x = fmaf(v.x, v.x, q.x); q.y = fmaf(v.y, v.y, q.y);
        q.z = fmaf(v.z, v.z, q.z); q.w = fmaf(v.w, v.w, q.w);
    }
#pragma unroll
    for (int o = 8; o < 32; o <<= 1) {
        s.x += __shfl_xor_sync(0xffffffffu, s.x, o);
        s.y += __shfl_xor_sync(0xffffffffu, s.y, o);
        s.z += __shfl_xor_sync(0xffffffffu, s.z, o);
        s.w += __shfl_xor_sync(0xffffffffu, s.w, o);
        q.x += __shfl_xor_sync(0xffffffffu, q.x, o);
        q.y += __shfl_xor_sync(0xffffffffu, q.y, o);
        q.z += __shfl_xor_sync(0xffffffffu, q.z, o);
        q.w += __shfl_xor_sync(0xffffffffu, q.w, o);
    }
    int lane = t & 31;
    if (lane < 8) {
        int off = (L == 1) ? 32 : 96;
        atomicAdd(&d_small[off + g + 0], s.x);
        atomicAdd(&d_small[off + g + 1], s.y);
        atomicAdd(&d_small[off + g + 2], s.z);
        atomicAdd(&d_small[off + g + 3], s.w);
        atomicAdd(&d_small[off + 32 + g + 0], q.x);
        atomicAdd(&d_small[off + 32 + g + 1], q.y);
        atomicAdd(&d_small[off + 32 + g + 2], q.z);
        atomicAdd(&d_small[off + 32 + g + 3], q.w);
    }

    // ---- last-block fused prep ----
    __shared__ bool isLast;
    __syncthreads();
    if (t == 0) {
        __threadfence();
        int prev = atomicAdd(&d_ctr[L - 1], 1);
        isLast = (prev == (int)gridDim.x - 1);
        if (isLast) d_ctr[L - 1] = 0;   // self-reset for next replay
    }
    __syncthreads();
    if (!isLast) return;

    if (L == 1) {
        // prep1: finalize BN1; build w2p = diag(s1)@w2 and c2 = t1@w2
        __shared__ float t1s[32];
        float sc = 0.f, tt = 0.f;
        if (t < 32) {
            float mu = __ldcg(&d_small[32 + t]) * (1.f / NNODES);
            float var = __ldcg(&d_small[64 + t]) * (1.f / NNODES) - mu * mu;
            sc = gam[t] * rsqrtf(var + 1e-5f);
            tt = bet[t] - mu * sc;
            t1s[t] = tt;
            d_prep[t] = sc; d_prep[32 + t] = tt;
        }
        __syncthreads();
        if (t < 32) {
            for (int h = 0; h < 32; h++) d_prep[64 + t * 32 + h] = sc * w2[t * 32 + h];
            float c = 0.f;
            for (int k = 0; k < 32; k++) c += t1s[k] * w2[k * 32 + t];
            d_prep[1088 + t] = c;
        }
    } else {
        // prep2: finalize BN2; fold BN1/BN2 into LSTM1; fold skip_avg into fc1 bias.
        __shared__ float s1s[32], t1s[32], s2s[32], t2s[32], xm[32];
        if (t < 32) {
            s1s[t] = d_prep[t]; t1s[t] = d_prep[32 + t];
            float mu = __ldcg(&d_small[96 + t]) * (1.f / NNODES);
            float var = __ldcg(&d_small[128 + t]) * (1.f / NNODES) - mu * mu;
            float sc = gam[t] * rsqrtf(var + 1e-5f);
            s2s[t] = sc; t2s[t] = bet[t] - mu * sc;
            xm[t] = d_small[t] * (1.f / NNODES);
        }
        __syncthreads();
        for (int i = t; i < 3072; i += 256) {
            int r = i >> 5, k = i & 31;
            int j = (r < 32) ? r : r + 32;
            d_prep2[i]        = s1s[k] * wih1[j * 64 + k];
            d_prep2[3072 + i] = s2s[k] * wih1[j * 64 + 32 + k];
            d_prep2[6144 + i] = wih2[j * 32 + k];
        }
        for (int r = t; r < 96; r += 256) {
            int j = (r < 32) ? r : r + 32;
            float gg = bih1[j] + bhh1[j];
            for (int k = 0; k < 32; k++)
                gg += t1s[k] * wih1[j * 64 + k] + t2s[k] * wih1[j * 64 + 32 + k];
            d_prep2[9216 + r] = gg;
            d_prep2[9312 + r] = bih2[j] + bhh2[j];
        }
        for (int o = t; o < 32; o += 256) {
            float v = fb1[o];
            for (int k = 0; k < 32; k++) v += fw1[o * 96 + 64 + k] * xm[k];
            d_prep2[9408 + o] = v;
        }
    }
}

// fused tail with packed f32x2 math; weight operands loaded as LDS.128 pairs.
__global__ __launch_bounds__(128) void k_final(const float* __restrict__ fw1,
                                               const float* __restrict__ fw2,
                                               const float* __restrict__ fb2,
                                               float* __restrict__ out) {
    __shared__ ull sA1p[1536], sA2p[1536], sW2p[1536], sF1p[1024];
    __shared__ float sGb1[96], sGb2[96], sFb1p[32], sFw2[32];
    __shared__ float sFb2v;
    int t = threadIdx.x;
    {
        float* fA1 = (float*)sA1p; float* fA2 = (float*)sA2p;
        float* fW2 = (float*)sW2p; float* fF1 = (float*)sF1p;
        for (int i = t; i < 3072; i += 128) {
            fA1[i] = d_prep2[i];
            fA2[i] = d_prep2[3072 + i];
            fW2[i] = d_prep2[6144 + i];
        }
        for (int i = t; i < 2048; i += 128) {
            int o = i >> 6, k = i & 63;
            fF1[i] = fw1[o * 96 + k];
        }
    }
    if (t < 96) { sGb1[t] = d_prep2[9216 + t]; sGb2[t] = d_prep2[9312 + t]; }
    if (t < 32) { sFb1p[t] = d_prep2[9408 + t]; sFw2[t] = fw2[t]; }
    if (t == 0) sFb2v = fb2[0];
    __syncthreads();

    int node = blockIdx.x * 128 + t;
    if (node >= NNODES) return;

    const ulonglong2* A1q = reinterpret_cast<const ulonglong2*>(sA1p);
    const ulonglong2* A2q = reinterpret_cast<const ulonglong2*>(sA2p);
    const ulonglong2* W2q = reinterpret_cast<const ulonglong2*>(sW2p);
    const ulonglong2* F1q = reinterpret_cast<const ulonglong2*>(sF1p);

    ull r1p[16], r2p[16];
    {
        const ulonglong2* q1 = reinterpret_cast<const ulonglong2*>(d_r1 + node * 32);
        const ulonglong2* q2 = reinterpret_cast<const ulonglong2*>(d_r2 + node * 32);
#pragma unroll
        for (int c = 0; c < 8; c++) {
            ulonglong2 a = q1[c]; r1p[2*c] = a.x; r1p[2*c+1] = a.y;
            ulonglong2 b = q2[c]; r2p[2*c] = b.x; r2p[2*c+1] = b.y;
        }
    }

    float hn1[32];
#pragma unroll
    for (int h = 0; h < 32; h++) {
        ull ai = pack2(sGb1[h], 0.f);
        ull ag = pack2(sGb1[32 + h], 0.f);
        ull ao = pack2(sGb1[64 + h], 0.f);
#pragma unroll
        for (int p = 0; p < 8; p++) {
            ulonglong2 wa1i = A1q[h * 8 + p];
            ulonglong2 wa2i = A2q[h * 8 + p];
            ulonglong2 wa1g = A1q[(32 + h) * 8 + p];
            ulonglong2 wa2g = A2q[(32 + h) * 8 + p];
            ulonglong2 wa1o = A1q[(64 + h) * 8 + p];
            ulonglong2 wa2o = A2q[(64 + h) * 8 + p];
            FMA2(ai, r1p[2*p],     wa1i.x, ai);
            FMA2(ai, r1p[2*p + 1], wa1i.y, ai);
            FMA2(ai, r2p[2*p],     wa2i.x, ai);
            FMA2(ai, r2p[2*p + 1], wa2i.y, ai);
            FMA2(ag, r1p[2*p],     wa1g.x, ag);
            FMA2(ag, r1p[2*p + 1], wa1g.y, ag);
            FMA2(ag, r2p[2*p],     wa2g.x, ag);
            FMA2(ag, r2p[2*p + 1], wa2g.y, ag);
            FMA2(ao, r1p[2*p],     wa1o.x, ao);
            FMA2(ao, r1p[2*p + 1], wa1o.y, ao);
            FMA2(ao, r2p[2*p],     wa2o.x, ao);
            FMA2(ao, r2p[2*p + 1], wa2o.y, ao);
        }
        float l0, l1, gi, gg, go;
        unpack2(ai, l0, l1); gi = l0 + l1;
        unpack2(ag, l0, l1); gg = l0 + l1;
        unpack2(ao, l0, l1); go = l0 + l1;
        float c = fsig(gi) * ftanh_(gg);
        hn1[h] = fsig(go) * ftanh_(c);
    }
    ull hn1p[16];
#pragma unroll
    for (int k2 = 0; k2 < 16; k2++) hn1p[k2] = pack2(hn1[2*k2], hn1[2*k2+1]);

    float hn2[32];
#pragma unroll
    for (int h = 0; h < 32; h++) {
        ull ai = pack2(sGb2[h], 0.f);
        ull ag = pack2(sGb2[32 + h], 0.f);
        ull ao = pack2(sGb2[64 + h], 0.f);
#pragma unroll
        for (int p = 0; p < 8; p++) {
            ulonglong2 wi = W2q[h * 8 + p];
            ulonglong2 wg = W2q[(32 + h) * 8 + p];
            ulonglong2 wo = W2q[(64 + h) * 8 + p];
            FMA2(ai, hn1p[2*p],     wi.x, ai);
            FMA2(ai, hn1p[2*p + 1], wi.y, ai);
            FMA2(ag, hn1p[2*p],     wg.x, ag);
            FMA2(ag, hn1p[2*p + 1], wg.y, ag);
            FMA2(ao, hn1p[2*p],     wo.x, ao);
            FMA2(ao, hn1p[2*p + 1], wo.y, ao);
        }
        float l0, l1, gi, gg, go;
        unpack2(ai, l0, l1); gi = l0 + l1;
        unpack2(ag, l0, l1); gg = l0 + l1;
        unpack2(ao, l0, l1); go = l0 + l1;
        float c = fsig(gi) * ftanh_(gg);
        hn2[h] = fsig(go) * ftanh_(c);
    }
    ull hn2p[16];
#pragma unroll
    for (int k2 = 0; k2 < 16; k2++) hn2p[k2] = pack2(hn2[2*k2], hn2[2*k2+1]);

    float acc = sFb2v;
#pragma unroll
    for (int o = 0; o < 32; o++) {
        ull a2 = pack2(sFb1p[o], 0.f);
#pragma unroll
        for (int p = 0; p < 8; p++) {
            ulonglong2 w1 = F1q[o * 16 + p];
            ulonglong2 w2v = F1q[o * 16 + 8 + p];
            FMA2(a2, hn1p[2*p],     w1.x, a2);
            FMA2(a2, hn1p[2*p + 1], w1.y, a2);
            FMA2(a2, hn2p[2*p],     w2v.x, a2);
            FMA2(a2, hn2p[2*p + 1], w2v.y, a2);
        }
        float l0, l1;
        unpack2(a2, l0, l1);
        acc = fmaf(fmaxf(l0 + l1, 0.f), sFw2[o], acc);
    }
    out[node] = acc;
}

// ---------------- launch ----------------
extern "C" void kernel_launch(void* const* d_in, const int* in_sizes, int n_in,
                              void* d_out, int out_size) {
    const float* x    = (const float*)d_in[0];
    const int*   ei   = (const int*)d_in[1];
    const float* ea   = (const float*)d_in[2];
    const float* w1   = (const float*)d_in[3];
    const float* b1   = (const float*)d_in[4];
    const float* g1   = (const float*)d_in[5];
    const float* be1  = (const float*)d_in[6];
    const float* w2   = (const float*)d_in[7];
    const float* b2   = (const float*)d_in[8];
    const float* g2   = (const float*)d_in[9];
    const float* be2  = (const float*)d_in[10];
    const float* wih1 = (const float*)d_in[11];
    const float* bih1 = (const float*)d_in[13];
    const float* bhh1 = (const float*)d_in[14];
    const float* wih2 = (const float*)d_in[15];
    const float* bih2 = (const float*)d_in[17];
    const float* bhh2 = (const float*)d_in[18];
    const float* fw1  = (const float*)d_in[19];
    const float* fb1  = (const float*)d_in[20];
    const float* fw2  = (const float*)d_in[21];
    const float* fb2  = (const float*)d_in[22];
    float* out = (float*)d_out;

    const int* src = ei;
    const int* dst = ei + NEDGES;

    const int NB_N  = (NNODES + 255) / 256;            // 391
    const int NB_Q  = (NEDGES / 4 + 255) / 256;        // 1563
    const int NB_E8 = (NEDGES / 4 * 8 + 255) / 256;    // 12500
    const int NB_G  = (NNODES + 255) / 256;            // 391 (gemm, 256-thread blocks)
    const int NB_F  = (NNODES + 127) / 128;            // 782
    const int NB_S  = 148;

    k_zero_all<<<NB_N, 256>>>();
    k_deg<<<NB_Q, 256>>>(dst, ea);
    k_colsum<<<NB_S, 256>>>(x);   // + fused nodeprep + agg zeroing

    // GCN layer 1
    k_gemm<1><<<NB_G, 256>>>(x, w1);
    k_edge<<<NB_E8, 256>>>(src, dst, ea);
    k_post<1><<<NB_S * 2, 256>>>(b1, g1, be1, w2,
                                 nullptr, nullptr, nullptr, nullptr,
                                 nullptr, nullptr, nullptr, nullptr);  // fused prep1

    // GCN layer 2
    k_gemm<2><<<NB_G, 256>>>(nullptr, nullptr);
    k_edge<<<NB_E8, 256>>>(src, dst, ea);
    k_post<2><<<NB_S * 2, 256>>>(b2, g2, be2, nullptr,
                                 wih1, bih1, bhh1, wih2,
                                 bih2, bhh2, fw1, fb1);                // fused prep2

    // fused tail
    k_final<<<NB_F, 128>>>(fw1, fw2, fb2, out);
}